// round 5
// baseline (speedup 1.0000x reference)
#include <cuda_runtime.h>
#include <stdint.h>

#define NB 8
#define NA 200000
#define NG 64
#define NK 4
#define NCHUNK 8
#define CHUNK 25000
#define GQ 4
#define MAXPOS 128

// ---------------- scratch (static __device__, no allocation) ----------------
__device__ unsigned long long g_part[NB * NG * NCHUNK * NK];  // chunk-partial top4 keys
__device__ float g_topval[NB][NG][NK];
__device__ int   g_topidx[NB][NG][NK];
__device__ unsigned long long g_poskeys[NB][NA];
__device__ int g_npos[NB];
__device__ int g_counts[NB][NG];

struct SplitKeys { unsigned int k[2 * NB]; };

// ---------------- threefry2x32 (exact JAX kernel: 20 rounds) ----------------
__host__ __device__ inline void threefry2x32(unsigned int k0, unsigned int k1,
                                             unsigned int c0, unsigned int c1,
                                             unsigned int &o0, unsigned int &o1) {
  unsigned int ks2 = 0x1BD11BDAu ^ k0 ^ k1;
  unsigned int x0 = c0 + k0, x1 = c1 + k1;
#define TFR(r) do { x0 += x1; x1 = (x1 << (r)) | (x1 >> (32 - (r))); x1 ^= x0; } while (0)
  TFR(13); TFR(15); TFR(26); TFR(6);
  x0 += k1;  x1 += ks2 + 1u;
  TFR(17); TFR(29); TFR(16); TFR(24);
  x0 += ks2; x1 += k0 + 2u;
  TFR(13); TFR(15); TFR(26); TFR(6);
  x0 += k0;  x1 += k1 + 3u;
  TFR(17); TFR(29); TFR(16); TFR(24);
  x0 += k1;  x1 += ks2 + 4u;
  TFR(13); TFR(15); TFR(26); TFR(6);
  x0 += ks2; x1 += k0 + 5u;
#undef TFR
  o0 = x0; o1 = x1;
}

// ---------------- IoU, bit-exact vs XLA (no contraction, IEEE div) ----------
__device__ __forceinline__ float iou_eval(float gx1, float gy1, float gx2, float gy2, float ga,
                                          float ax1, float ay1, float ax2, float ay2, float aa) {
  float ltx = fmaxf(gx1, ax1);
  float lty = fmaxf(gy1, ay1);
  float rbx = fminf(gx2, ax2);
  float rby = fminf(gy2, ay2);
  float wx = fmaxf(__fsub_rn(rbx, ltx), 0.0f);
  float wy = fmaxf(__fsub_rn(rby, lty), 0.0f);
  float inter = __fmul_rn(wx, wy);
  if (inter == 0.0f) return 0.0f;                     // 0/union == +0 exactly
  float uni = __fsub_rn(__fadd_rn(ga, aa), inter);    // (a1+a2)-inter, XLA order
  return __fdiv_rn(inter, uni);
}

// insert key into descending sorted 4-list; caller guarantees key > t[3]
__device__ __forceinline__ void insert4(unsigned long long *t, unsigned long long key) {
  if (key > t[1]) {
    t[3] = t[2]; t[2] = t[1];
    if (key > t[0]) { t[1] = t[0]; t[0] = key; } else { t[1] = key; }
  } else {
    if (key > t[2]) { t[3] = t[2]; t[2] = key; } else { t[3] = key; }
  }
}

// merge two descending sorted 4-lists -> top4 into a
__device__ __forceinline__ void merge4(unsigned long long *a, const unsigned long long *b) {
  unsigned long long out[4];
  int i = 0, j = 0;
#pragma unroll
  for (int k = 0; k < 4; k++) {
    unsigned long long av = a[i], bv = b[j];
    if (av >= bv) { out[k] = av; i++; } else { out[k] = bv; j++; }
  }
#pragma unroll
  for (int k = 0; k < 4; k++) a[k] = out[k];
}

__global__ void init_kernel() {
  if (threadIdx.x < NB) g_npos[threadIdx.x] = 0;
}

// ---------------- phase 1: per-GT top-4 over anchors (GT-major) -------------
// grid: x = anchor chunk (8), y = gt group (16 groups of 4), z = image (8)
__global__ void __launch_bounds__(256) phase1_kernel(const float *__restrict__ anchors,
                                                     const float *__restrict__ gt) {
  const int b = blockIdx.z;
  const int g0 = blockIdx.y * GQ;
  const int ch = blockIdx.x;
  const int tid = threadIdx.x;

  __shared__ float sg[GQ][5];
  if (tid < GQ) {
    const float *gp = gt + (size_t)(b * NG + g0 + tid) * 4;
    float cx = gp[0], cy = gp[1], w = gp[2], h = gp[3];
    float tx = __fmul_rn(0.5f, w), ty = __fmul_rn(0.5f, h);
    float x1 = __fsub_rn(cx, tx), x2 = __fadd_rn(cx, tx);
    float y1 = __fsub_rn(cy, ty), y2 = __fadd_rn(cy, ty);
    sg[tid][0] = x1; sg[tid][1] = y1; sg[tid][2] = x2; sg[tid][3] = y2;
    sg[tid][4] = __fmul_rn(__fsub_rn(x2, x1), __fsub_rn(y2, y1));
  }
  __syncthreads();

  float gx1[GQ], gy1[GQ], gx2[GQ], gy2[GQ], ga[GQ];
#pragma unroll
  for (int j = 0; j < GQ; j++) {
    gx1[j] = sg[j][0]; gy1[j] = sg[j][1]; gx2[j] = sg[j][2]; gy2[j] = sg[j][3]; ga[j] = sg[j][4];
  }

  unsigned long long top[GQ][4];
#pragma unroll
  for (int j = 0; j < GQ; j++)
#pragma unroll
    for (int k = 0; k < 4; k++) top[j][k] = 0ull;

  const int a0 = ch * CHUNK;
  const float4 *ap = reinterpret_cast<const float4 *>(anchors) + (size_t)b * NA;
  for (int a = a0 + tid; a < a0 + CHUNK; a += 256) {
    float4 v = ap[a];
    float tx = __fmul_rn(0.5f, v.z), ty = __fmul_rn(0.5f, v.w);
    float ax1 = __fsub_rn(v.x, tx), ax2 = __fadd_rn(v.x, tx);
    float ay1 = __fsub_rn(v.y, ty), ay2 = __fadd_rn(v.y, ty);
    float aa = __fmul_rn(__fsub_rn(ax2, ax1), __fsub_rn(ay2, ay1));
    unsigned int idxk = 0xFFFFFFFFu - (unsigned int)a;  // ties -> lower index wins
#pragma unroll
    for (int j = 0; j < GQ; j++) {
      float iou = iou_eval(gx1[j], gy1[j], gx2[j], gy2[j], ga[j], ax1, ay1, ax2, ay2, aa);
      unsigned long long key = ((unsigned long long)__float_as_uint(iou) << 32) | idxk;
      if (key > top[j][3]) insert4(top[j], key);
    }
  }

  __shared__ unsigned long long red[256 * 4];
  for (int j = 0; j < GQ; j++) {
#pragma unroll
    for (int k = 0; k < 4; k++) red[tid * 4 + k] = top[j][k];
    __syncthreads();
    for (int s = 128; s > 0; s >>= 1) {
      if (tid < s) merge4(&red[tid * 4], &red[(tid + s) * 4]);
      __syncthreads();
    }
    if (tid == 0) {
      size_t base = (size_t)((b * NG + g0 + j) * NCHUNK + ch) * 4;
#pragma unroll
      for (int k = 0; k < 4; k++) g_part[base + k] = red[k];
    }
    __syncthreads();
  }
}

// ---------------- phase 1b: merge chunk partials ----------------------------
__global__ void merge_parts_kernel() {
  int t = blockIdx.x * blockDim.x + threadIdx.x;
  if (t >= NB * NG) return;
  unsigned long long best[4] = {0ull, 0ull, 0ull, 0ull};
  for (int c = 0; c < NCHUNK; c++) {
    const unsigned long long *p = &g_part[(size_t)(t * NCHUNK + c) * 4];
#pragma unroll
    for (int k = 0; k < 4; k++) {
      unsigned long long key = p[k];
      if (key > best[3]) insert4(best, key);
    }
  }
  int b = t >> 6, g = t & 63;
#pragma unroll
  for (int k = 0; k < 4; k++) {
    g_topval[b][g][k] = __uint_as_float((unsigned int)(best[k] >> 32));
    g_topidx[b][g][k] = (int)(0xFFFFFFFFu - (unsigned int)best[k]);
  }
}

// ---------------- phase 2: anchor-major labeling + positive collection ------
// grid: x = anchor blocks (782), y = image (8)
__global__ void __launch_bounds__(256) phase2_kernel(const float *__restrict__ anchors,
                                                     const float *__restrict__ gt,
                                                     SplitKeys sk) {
  const int b = blockIdx.y;
  const int tid = threadIdx.x;
  __shared__ float4 sbox[NG];
  __shared__ float2 sah[NG];  // (area, hq)
  if (tid < NG) {
    const float *gp = gt + (size_t)(b * NG + tid) * 4;
    float cx = gp[0], cy = gp[1], w = gp[2], h = gp[3];
    float tx = __fmul_rn(0.5f, w), ty = __fmul_rn(0.5f, h);
    float x1 = __fsub_rn(cx, tx), x2 = __fadd_rn(cx, tx);
    float y1 = __fsub_rn(cy, ty), y2 = __fadd_rn(cy, ty);
    sbox[tid] = make_float4(x1, y1, x2, y2);
    sah[tid] = make_float2(__fmul_rn(__fsub_rn(x2, x1), __fsub_rn(y2, y1)),
                           g_topval[b][tid][0]);
  }
  __syncthreads();
  int a = blockIdx.x * 256 + tid;
  if (a >= NA) return;  // NA % 32 == 0 -> warp-uniform exit, ballot below safe

  float4 v = reinterpret_cast<const float4 *>(anchors)[(size_t)b * NA + a];
  float tx = __fmul_rn(0.5f, v.z), ty = __fmul_rn(0.5f, v.w);
  float ax1 = __fsub_rn(v.x, tx), ax2 = __fadd_rn(v.x, tx);
  float ay1 = __fsub_rn(v.y, ty), ay2 = __fadd_rn(v.y, ty);
  float aa = __fmul_rn(__fsub_rn(ax2, ax1), __fsub_rn(ay2, ay1));

  float best = -1.0f;
  int bg = 0;
  bool eq = false;
#pragma unroll 8
  for (int g = 0; g < NG; g++) {
    float4 gb = sbox[g];
    float2 ah = sah[g];
    float iou = iou_eval(gb.x, gb.y, gb.z, gb.w, ah.x, ax1, ay1, ax2, ay2, aa);
    eq |= (iou == ah.y);                   // low-quality match (exact equality)
    if (iou > best) { best = iou; bg = g; }  // first-max == jnp.argmax
  }
  bool pos = (best >= 0.7f) || eq;

  // warp-aggregated append of subsample keys for positives
  unsigned int mask = __ballot_sync(0xFFFFFFFFu, pos);
  if (pos) {
    // JAX partitionable uniform bits for element a:
    //   (o0, o1) = threefry(key_b, (hi, lo) of 64-bit index) ; bits = o0 ^ o1
    unsigned int o0, o1;
    threefry2x32(sk.k[2 * b], sk.k[2 * b + 1], 0u, (unsigned int)a, o0, o1);
    unsigned int u = o0 ^ o1;
    float f = __uint_as_float((u >> 9) | 0x3f800000u);
    unsigned int rb = __float_as_uint(__fsub_rn(f, 1.0f));  // exact: f in [1,2)
    unsigned long long key =
        ((unsigned long long)rb << 32) | (unsigned int)(a * 64 + bg);
    int lane = tid & 31;
    int leader = __ffs(mask) - 1;
    int base = 0;
    if (lane == leader) base = atomicAdd(&g_npos[b], __popc(mask));
    base = __shfl_sync(mask, base, leader);
    int off = __popc(mask & ((1u << lane) - 1u));
    g_poskeys[b][base + off] = key;
  }
}

// ---------------- phase 3: select 128 smallest keys, count per GT -----------
__global__ void __launch_bounds__(1024) phase3_kernel() {
  const int b = blockIdx.x;
  const int tid = threadIdx.x;
  const int n = g_npos[b];
  __shared__ int hist[256];
  __shared__ unsigned long long s_prefix;
  __shared__ int s_want;

  unsigned long long thresh;
  if (n <= MAXPOS) {
    thresh = ~0ull;  // select all positives
  } else {
    if (tid == 0) { s_prefix = 0ull; s_want = MAXPOS; }
    __syncthreads();
    for (int shift = 56; shift >= 0; shift -= 8) {
      if (tid < 256) hist[tid] = 0;
      __syncthreads();
      unsigned long long pref = s_prefix;
      for (int i = tid; i < n; i += 1024) {
        unsigned long long k = g_poskeys[b][i];
        bool match = (shift == 56) ? true
                                   : ((k >> (shift + 8)) == (pref >> (shift + 8)));
        if (match) atomicAdd(&hist[(int)((k >> shift) & 255u)], 1);
      }
      __syncthreads();
      if (tid == 0) {
        int want = s_want;
        int d = 0;
        for (; d < 256; d++) {
          if (want <= hist[d]) break;
          want -= hist[d];
        }
        s_prefix = pref | ((unsigned long long)d << shift);
        s_want = want;
      }
      __syncthreads();
    }
    thresh = s_prefix;  // exact 128th-smallest key (keys unique)
  }

  __shared__ int cnt[NG];
  if (tid < NG) cnt[tid] = 0;
  __syncthreads();
  for (int i = tid; i < n; i += 1024) {
    unsigned long long k = g_poskeys[b][i];
    if (k <= thresh) atomicAdd(&cnt[(int)(k & 63u)], 1);
  }
  __syncthreads();
  if (tid < NG) g_counts[b][tid] = cnt[tid];
}

// ---------------- phase 4: emit [pr | gt | valid | scores] as float32 -------
__global__ void write_out_kernel(float *__restrict__ out) {
  int t = blockIdx.x * blockDim.x + threadIdx.x;
  if (t >= NB * NG * NK) return;
  int b = t >> 8;
  int g = (t >> 2) & 63;
  int k = t & 3;
  int c = g_counts[b][g];
  if (c > NK) c = NK;
  bool valid = k < c;
  float val = g_topval[b][g][k];
  int idx = g_topidx[b][g][k];
  const int SEC = NB * NG * NK;  // 2048
  int o = b * (NG * NK) + g * NK + k;
  out[o]           = valid ? (float)idx : -1.0f;
  out[SEC + o]     = valid ? (float)g : -1.0f;
  out[2 * SEC + o] = valid ? 1.0f : 0.0f;
  out[3 * SEC + o] = valid ? val : 0.0f;
}

// ---------------- launch -----------------------------------------------------
extern "C" void kernel_launch(void *const *d_in, const int *in_sizes, int n_in,
                              void *d_out, int out_size) {
  const float *anchors = (const float *)d_in[0];   // [8, 200000, 4] cxcywh
  const float *gt      = (const float *)d_in[1];   // [8, 64, 4] cxcywh

  // JAX partitionable split (foldlike): key_b = threefry((0,42), (0,b)), both words
  SplitKeys sk;
  for (int b = 0; b < NB; b++) {
    unsigned int o0, o1;
    threefry2x32(0u, 42u, 0u, (unsigned int)b, o0, o1);
    sk.k[2 * b] = o0;
    sk.k[2 * b + 1] = o1;
  }

  init_kernel<<<1, 32>>>();
  phase1_kernel<<<dim3(NCHUNK, NG / GQ, NB), 256>>>(anchors, gt);
  merge_parts_kernel<<<2, 256>>>();
  phase2_kernel<<<dim3((NA + 255) / 256, NB), 256>>>(anchors, gt, sk);
  phase3_kernel<<<NB, 1024>>>();
  write_out_kernel<<<NB, 256>>>((float *)d_out);
}